// round 1
// baseline (speedup 1.0000x reference)
#include <cuda_runtime.h>
#include <cstdint>

#define WIDTH  1024
#define HALF   512
#define DEPTH  8
#define BDEPTH 10
#define BATCH  65536

typedef unsigned long long ull;

// Coefficient tables (precomputed per launch by prep kernels).
// g_ctab: per (global step T=layer*10+t, entry) -> (c, c, s, s) float4
//   reg-bit steps:  entry = pairidx*32 + lane        (512 entries/step)
//   lane-bit steps: entry = slot*16 + lanepair        (512 entries/step)
__device__ float4 g_ctab[DEPTH * BDEPTH * 512];
// quintic params per (act_layer, slot*32+lane): (m,m,nb,nb) with m=slope/scale, nb=-bias/scale
__device__ float4 g_qa[(DEPTH - 1) * 1024];
// (scale, scale)
__device__ float2 g_qs[(DEPTH - 1) * 1024];

// ---------- f32x2 helpers ----------
__device__ __forceinline__ ull pk(float lo, float hi) {
    ull r;
    asm("mov.b64 %0, {%1, %2};" : "=l"(r) : "r"(__float_as_uint(lo)), "r"(__float_as_uint(hi)));
    return r;
}
__device__ __forceinline__ void unpk(ull v, float& lo, float& hi) {
    unsigned a, b;
    asm("mov.b64 {%0, %1}, %2;" : "=r"(a), "=r"(b) : "l"(v));
    lo = __uint_as_float(a);
    hi = __uint_as_float(b);
}
__device__ __forceinline__ ull f2mul(ull a, ull b) {
    ull r;
    asm("mul.rn.f32x2 %0, %1, %2;" : "=l"(r) : "l"(a), "l"(b));
    return r;
}
__device__ __forceinline__ ull f2fma(ull a, ull b, ull c) {
    ull r;
    asm("fma.rn.f32x2 %0, %1, %2, %3;" : "=l"(r) : "l"(a), "l"(b), "l"(c));
    return r;
}

// ---------- prep: coefficient table ----------
// Element index p0 (10 bits) maps to (slot v in [0,32), lane l in [0,32)):
//   p0 = (v_hi << 7) | (l << 2) | v_lo   where v = (v_hi<<2)|v_lo
// So p0 bits: [1:0]=slot bits[1:0], [6:2]=lane bits, [9:7]=slot bits[4:2].
// Step t (in layer) pairs original bit b = 9 - t.
// theta index: j bit k = p0 bit ((k - t) mod 10), k=0..8; theta = bparams[layer][j][t].
__global__ void prep_ctab(const float* __restrict__ bp) {
    int e = blockIdx.x * blockDim.x + threadIdx.x;
    if (e >= DEPTH * BDEPTH * 512) return;
    int T = e >> 9;
    int idx = e & 511;
    int layer = T / BDEPTH;
    int t = T % BDEPTH;
    int b = 9 - t;

    int v0, l0;
    if (b >= 7 || b <= 1) {
        // register-bit step: slot bit = (b>=7 ? b-7+2 : b)
        int sbit = (b >= 7) ? (b - 5) : b;
        int m = 1 << sbit;
        int pi = idx >> 5;
        l0 = idx & 31;
        v0 = (pi & (m - 1)) | ((pi & ~(m - 1)) << 1);
    } else {
        // lane-bit step: lane bit = b-2
        int lm = 1 << (b - 2);
        int v = idx >> 4;
        int lp = idx & 15;
        l0 = (lp & (lm - 1)) | ((lp & ~(lm - 1)) << 1);
        v0 = v;
    }
    int p0 = ((v0 >> 2) << 7) | (l0 << 2) | (v0 & 3);  // bit-b == 0 member of the pair

    int j = 0;
#pragma unroll
    for (int k = 0; k < 9; k++) {
        int src = ((k - t) % 10 + 10) % 10;
        j |= ((p0 >> src) & 1) << k;
    }
    float theta = bp[layer * (HALF * BDEPTH) + j * BDEPTH + t];
    float s, c;
    sincosf(theta, &s, &c);
    g_ctab[e] = make_float4(c, c, s, s);
}

__global__ void prep_qtab(const float* __restrict__ bias,
                          const float* __restrict__ slope,
                          const float* __restrict__ scale) {
    int e = blockIdx.x * blockDim.x + threadIdx.x;
    if (e >= (DEPTH - 1) * 1024) return;
    int act = e >> 10;
    int idx = e & 1023;
    int v = idx >> 5;
    int l = idx & 31;
    int p0 = ((v >> 2) << 7) | (l << 2) | (v & 3);
    float bi = bias[act * WIDTH + p0];
    float sl = slope[act * WIDTH + p0];
    float sc = scale[act * WIDTH + p0];
    float m = sl / sc;
    float nb = -bi / sc;
    g_qa[e] = make_float4(m, m, nb, nb);
    g_qs[e] = make_float2(sc, sc);
}

// ---------- main kernel ----------
// Each warp processes 4 rows. Thread holds 32 slots x 2 f32x2 values (rows 0,1 | rows 2,3).
// val[v*2 + h].

template <int M>
__device__ __forceinline__ void reg_step(ull (&val)[64], int lane, const float4* __restrict__ ct) {
#pragma unroll
    for (int pi = 0; pi < 16; pi++) {
        const int v0 = (pi & (M - 1)) | ((pi & ~(M - 1)) << 1);
        const int v1 = v0 | M;
        float4 cs = __ldg(ct + pi * 32 + lane);
        ull c2 = pk(cs.x, cs.y);
        ull s2 = pk(cs.z, cs.w);
        ull ns2 = s2 ^ 0x8000000080000000ULL;
#pragma unroll
        for (int h = 0; h < 2; h++) {
            ull x0 = val[v0 * 2 + h];
            ull x1 = val[v1 * 2 + h];
            val[v0 * 2 + h] = f2fma(c2, x0, f2mul(s2, x1));   // n0 =  c*x0 + s*x1
            val[v1 * 2 + h] = f2fma(c2, x1, f2mul(ns2, x0));  // n1 =  c*x1 - s*x0
        }
    }
}

template <int LM>
__device__ __forceinline__ void lane_step(ull (&val)[64], int lane, const float4* __restrict__ ct) {
    const ull smask = (lane & LM) ? 0x8000000080000000ULL : 0ULL;
    const int lp = (lane & (LM - 1)) | ((lane >> 1) & ~(LM - 1));
#pragma unroll
    for (int v = 0; v < 32; v++) {
        float4 cs = __ldg(ct + v * 16 + lp);
        ull c2 = pk(cs.x, cs.y);
        ull s2 = pk(cs.z, cs.w) ^ smask;
#pragma unroll
        for (int h = 0; h < 2; h++) {
            ull x = val[v * 2 + h];
            ull xp = __shfl_xor_sync(0xffffffffu, x, LM);
            val[v * 2 + h] = f2fma(c2, x, f2mul(s2, xp));
        }
    }
}

__device__ __forceinline__ void quintic(ull (&val)[64], int lane, int act) {
    const float4* __restrict__ qa = g_qa + act * 1024;
    const float2* __restrict__ qs = g_qs + act * 1024;
    const ull C1875 = 0x3FF000003FF00000ULL;  // (1.875, 1.875)
    const ull CM125 = 0xBFA00000BFA00000ULL;  // (-1.25, -1.25)
    const ull C0375 = 0x3EC000003EC00000ULL;  // (0.375, 0.375)
#pragma unroll
    for (int v = 0; v < 32; v++) {
        float4 aq = __ldg(qa + v * 32 + lane);
        float2 sq = __ldg(qs + v * 32 + lane);
        ull m2 = pk(aq.x, aq.y);
        ull nb2 = pk(aq.z, aq.w);
        ull sc2 = pk(sq.x, sq.y);
#pragma unroll
        for (int h = 0; h < 2; h++) {
            ull u = f2fma(val[v * 2 + h], m2, nb2);
            float lo, hi;
            unpk(u, lo, hi);
            lo = fminf(fmaxf(lo, -1.0f), 1.0f);
            hi = fminf(fmaxf(hi, -1.0f), 1.0f);
            u = pk(lo, hi);
            ull u2 = f2mul(u, u);
            ull p = f2fma(u2, C0375, CM125);
            p = f2fma(u2, p, C1875);
            ull r = f2mul(u, p);
            val[v * 2 + h] = f2mul(r, sc2);
        }
    }
}

__global__ void __launch_bounds__(128, 1)
net_kernel(const float* __restrict__ X, float* __restrict__ Y) {
    const int lane = threadIdx.x & 31;
    const int w = blockIdx.x * 4 + (threadIdx.x >> 5);
    const long long row0 = (long long)w * 4;
    const float* __restrict__ xr0 = X + row0 * WIDTH;
    const float* __restrict__ xr1 = xr0 + WIDTH;
    const float* __restrict__ xr2 = xr1 + WIDTH;
    const float* __restrict__ xr3 = xr2 + WIDTH;

    ull val[64];

    // load: 4 rows, packed (row0,row1) -> h=0, (row2,row3) -> h=1
#pragma unroll
    for (int vhi = 0; vhi < 8; vhi++) {
        int off = vhi * 128 + lane * 4;
        float4 a = *(const float4*)(xr0 + off);
        float4 b = *(const float4*)(xr1 + off);
        float4 c = *(const float4*)(xr2 + off);
        float4 d = *(const float4*)(xr3 + off);
        int s = vhi * 4;
        val[(s + 0) * 2 + 0] = pk(a.x, b.x);  val[(s + 0) * 2 + 1] = pk(c.x, d.x);
        val[(s + 1) * 2 + 0] = pk(a.y, b.y);  val[(s + 1) * 2 + 1] = pk(c.y, d.y);
        val[(s + 2) * 2 + 0] = pk(a.z, b.z);  val[(s + 2) * 2 + 1] = pk(c.z, d.z);
        val[(s + 3) * 2 + 0] = pk(a.w, b.w);  val[(s + 3) * 2 + 1] = pk(c.w, d.w);
    }

#pragma unroll 1
    for (int layer = 0; layer < DEPTH; layer++) {
        const float4* __restrict__ ct = g_ctab + layer * (BDEPTH * 512);
        reg_step<16>(val, lane, ct + 0 * 512);   // t=0: bit 9
        reg_step<8>(val, lane, ct + 1 * 512);    // t=1: bit 8
        reg_step<4>(val, lane, ct + 2 * 512);    // t=2: bit 7
        lane_step<16>(val, lane, ct + 3 * 512);  // t=3: bit 6
        lane_step<8>(val, lane, ct + 4 * 512);   // t=4: bit 5
        lane_step<4>(val, lane, ct + 5 * 512);   // t=5: bit 4
        lane_step<2>(val, lane, ct + 6 * 512);   // t=6: bit 3
        lane_step<1>(val, lane, ct + 7 * 512);   // t=7: bit 2
        reg_step<2>(val, lane, ct + 8 * 512);    // t=8: bit 1
        reg_step<1>(val, lane, ct + 9 * 512);    // t=9: bit 0
        if (layer < DEPTH - 1) quintic(val, lane, layer);
    }

    // store (final permutation is identity: 80 steps = 8 full index rotations)
    float* __restrict__ yr0 = Y + row0 * WIDTH;
    float* __restrict__ yr1 = yr0 + WIDTH;
    float* __restrict__ yr2 = yr1 + WIDTH;
    float* __restrict__ yr3 = yr2 + WIDTH;
#pragma unroll
    for (int vhi = 0; vhi < 8; vhi++) {
        int off = vhi * 128 + lane * 4;
        float4 a, b, c, d;
        int s = vhi * 4;
        unpk(val[(s + 0) * 2 + 0], a.x, b.x);  unpk(val[(s + 0) * 2 + 1], c.x, d.x);
        unpk(val[(s + 1) * 2 + 0], a.y, b.y);  unpk(val[(s + 1) * 2 + 1], c.y, d.y);
        unpk(val[(s + 2) * 2 + 0], a.z, b.z);  unpk(val[(s + 2) * 2 + 1], c.z, d.z);
        unpk(val[(s + 3) * 2 + 0], a.w, b.w);  unpk(val[(s + 3) * 2 + 1], c.w, d.w);
        *(float4*)(yr0 + off) = a;
        *(float4*)(yr1 + off) = b;
        *(float4*)(yr2 + off) = c;
        *(float4*)(yr3 + off) = d;
    }
}

extern "C" void kernel_launch(void* const* d_in, const int* in_sizes, int n_in,
                              void* d_out, int out_size) {
    const float* X     = (const float*)d_in[0];
    const float* bp    = (const float*)d_in[1];
    const float* bias  = (const float*)d_in[2];
    const float* slope = (const float*)d_in[3];
    const float* scale = (const float*)d_in[4];
    float* Y = (float*)d_out;

    prep_ctab<<<(DEPTH * BDEPTH * 512) / 256, 256>>>(bp);
    prep_qtab<<<((DEPTH - 1) * 1024) / 256, 256>>>(bias, slope, scale);
    // 4 rows per warp, 4 warps per CTA -> 16 rows per CTA
    net_kernel<<<BATCH / 16, 128>>>(X, Y);
}

// round 2
// speedup vs baseline: 1.0049x; 1.0049x over previous
#include <cuda_runtime.h>
#include <cstdint>

#define WIDTH  1024
#define HALF   512
#define DEPTH  8
#define BDEPTH 10
#define BATCH  65536

typedef unsigned long long ull;

// Coefficient tables (precomputed per launch by the prep kernel).
// g_ctab: per (global step T=layer*10+t, entry) -> (c, c, s, s) float4
//   reg-bit steps:  entry = pairidx*32 + lane        (512 entries/step)
//   lane-bit steps: entry = slot*16 + lanepair       (512 entries/step)
__device__ float4 g_ctab[DEPTH * BDEPTH * 512];
// quintic params per (act_layer, slot*32+lane): (m,m,nb,nb) with m=slope/scale, nb=-bias/scale
__device__ float4 g_qa[(DEPTH - 1) * 1024];
// (scale, scale)
__device__ float2 g_qs[(DEPTH - 1) * 1024];

// ---------- f32x2 helpers ----------
__device__ __forceinline__ ull pk(float lo, float hi) {
    ull r;
    asm("mov.b64 %0, {%1, %2};" : "=l"(r) : "r"(__float_as_uint(lo)), "r"(__float_as_uint(hi)));
    return r;
}
__device__ __forceinline__ void unpk(ull v, float& lo, float& hi) {
    unsigned a, b;
    asm("mov.b64 {%0, %1}, %2;" : "=r"(a), "=r"(b) : "l"(v));
    lo = __uint_as_float(a);
    hi = __uint_as_float(b);
}
__device__ __forceinline__ ull f2mul(ull a, ull b) {
    ull r;
    asm("mul.rn.f32x2 %0, %1, %2;" : "=l"(r) : "l"(a), "l"(b));
    return r;
}
__device__ __forceinline__ ull f2fma(ull a, ull b, ull c) {
    ull r;
    asm("fma.rn.f32x2 %0, %1, %2, %3;" : "=l"(r) : "l"(a), "l"(b), "l"(c));
    return r;
}
// Compiler fence: stops NVVM/ptxas from hoisting coefficient loads arbitrarily far,
// bounding in-flight registers (val[] stays in regs, unaffected).
__device__ __forceinline__ void cfence() { asm volatile("" ::: "memory"); }

// ---------- prep: all coefficient tables in ONE launch ----------
// Element index p0 (10 bits) maps to (slot v in [0,32), lane l in [0,32)):
//   p0 = (v_hi << 7) | (l << 2) | v_lo   where v = (v_hi<<2)|v_lo
// Step t (in layer) pairs original bit b = 9 - t.
// theta index: j bit k = p0 bit ((k - t) mod 10), k=0..8; theta = bparams[layer][j][t].
#define CT_ELEMS (DEPTH * BDEPTH * 512)
#define Q_ELEMS  ((DEPTH - 1) * 1024)

__global__ void prep_all(const float* __restrict__ bp,
                         const float* __restrict__ bias,
                         const float* __restrict__ slope,
                         const float* __restrict__ scale) {
    int e = blockIdx.x * blockDim.x + threadIdx.x;
    if (e < CT_ELEMS) {
        int T = e >> 9;
        int idx = e & 511;
        int layer = T / BDEPTH;
        int t = T % BDEPTH;
        int b = 9 - t;

        int v0, l0;
        if (b >= 7 || b <= 1) {
            int sbit = (b >= 7) ? (b - 5) : b;
            int m = 1 << sbit;
            int pi = idx >> 5;
            l0 = idx & 31;
            v0 = (pi & (m - 1)) | ((pi & ~(m - 1)) << 1);
        } else {
            int lm = 1 << (b - 2);
            int v = idx >> 4;
            int lp = idx & 15;
            l0 = (lp & (lm - 1)) | ((lp & ~(lm - 1)) << 1);
            v0 = v;
        }
        int p0 = ((v0 >> 2) << 7) | (l0 << 2) | (v0 & 3);

        int j = 0;
#pragma unroll
        for (int k = 0; k < 9; k++) {
            int src = ((k - t) % 10 + 10) % 10;
            j |= ((p0 >> src) & 1) << k;
        }
        float theta = bp[layer * (HALF * BDEPTH) + j * BDEPTH + t];
        float s, c;
        sincosf(theta, &s, &c);
        g_ctab[e] = make_float4(c, c, s, s);
    } else if (e < CT_ELEMS + Q_ELEMS) {
        int q = e - CT_ELEMS;
        int act = q >> 10;
        int idx = q & 1023;
        int v = idx >> 5;
        int l = idx & 31;
        int p0 = ((v >> 2) << 7) | (l << 2) | (v & 3);
        float bi = bias[act * WIDTH + p0];
        float sl = slope[act * WIDTH + p0];
        float sc = scale[act * WIDTH + p0];
        g_qa[q] = make_float4(sl / sc, sl / sc, -bi / sc, -bi / sc);
        g_qs[q] = make_float2(sc, sc);
    }
}

// ---------- main kernel ----------
// Each warp processes 4 rows. Thread holds 32 slots x 2 f32x2 values (rows 0,1 | rows 2,3).
// val[v*2 + h].

template <int M>
__device__ __forceinline__ void reg_step(ull (&val)[64], int lane, const float4* __restrict__ ct) {
#pragma unroll
    for (int pi = 0; pi < 16; pi++) {
        const int v0 = (pi & (M - 1)) | ((pi & ~(M - 1)) << 1);
        const int v1 = v0 | M;
        float4 cs = __ldg(ct + pi * 32 + lane);
        ull c2 = pk(cs.x, cs.y);
        ull s2 = pk(cs.z, cs.w);
        ull ns2 = s2 ^ 0x8000000080000000ULL;
#pragma unroll
        for (int h = 0; h < 2; h++) {
            ull x0 = val[v0 * 2 + h];
            ull x1 = val[v1 * 2 + h];
            val[v0 * 2 + h] = f2fma(c2, x0, f2mul(s2, x1));   // n0 =  c*x0 + s*x1
            val[v1 * 2 + h] = f2fma(c2, x1, f2mul(ns2, x0));  // n1 =  c*x1 - s*x0
        }
        if ((pi & 3) == 3) cfence();
    }
}

template <int LM>
__device__ __forceinline__ void lane_step(ull (&val)[64], int lane, const float4* __restrict__ ct) {
    const ull smask = (lane & LM) ? 0x8000000080000000ULL : 0ULL;
    const int lp = (lane & (LM - 1)) | ((lane >> 1) & ~(LM - 1));
#pragma unroll
    for (int v = 0; v < 32; v++) {
        float4 cs = __ldg(ct + v * 16 + lp);
        ull c2 = pk(cs.x, cs.y);
        ull s2 = pk(cs.z, cs.w) ^ smask;
#pragma unroll
        for (int h = 0; h < 2; h++) {
            ull x = val[v * 2 + h];
            ull xp = __shfl_xor_sync(0xffffffffu, x, LM);
            val[v * 2 + h] = f2fma(c2, x, f2mul(s2, xp));
        }
        if ((v & 7) == 7) cfence();
    }
}

__device__ __forceinline__ void quintic(ull (&val)[64], int lane, int act) {
    const float4* __restrict__ qa = g_qa + act * 1024;
    const float2* __restrict__ qs = g_qs + act * 1024;
    const ull C1875 = 0x3FF000003FF00000ULL;  // (1.875, 1.875)
    const ull CM125 = 0xBFA00000BFA00000ULL;  // (-1.25, -1.25)
    const ull C0375 = 0x3EC000003EC00000ULL;  // (0.375, 0.375)
#pragma unroll
    for (int v = 0; v < 32; v++) {
        float4 aq = __ldg(qa + v * 32 + lane);
        float2 sq = __ldg(qs + v * 32 + lane);
        ull m2 = pk(aq.x, aq.y);
        ull nb2 = pk(aq.z, aq.w);
        ull sc2 = pk(sq.x, sq.y);
#pragma unroll
        for (int h = 0; h < 2; h++) {
            ull u = f2fma(val[v * 2 + h], m2, nb2);
            float lo, hi;
            unpk(u, lo, hi);
            lo = fminf(fmaxf(lo, -1.0f), 1.0f);
            hi = fminf(fmaxf(hi, -1.0f), 1.0f);
            u = pk(lo, hi);
            ull u2 = f2mul(u, u);
            ull p = f2fma(u2, C0375, CM125);
            p = f2fma(u2, p, C1875);
            ull r = f2mul(u, p);
            val[v * 2 + h] = f2mul(r, sc2);
        }
        if ((v & 7) == 7) cfence();
    }
}

__global__ void __launch_bounds__(128, 1)
net_kernel(const float* __restrict__ X, float* __restrict__ Y) {
    const int lane = threadIdx.x & 31;
    const int w = blockIdx.x * 4 + (threadIdx.x >> 5);
    const long long row0 = (long long)w * 4;
    const float* __restrict__ xr0 = X + row0 * WIDTH;
    const float* __restrict__ xr1 = xr0 + WIDTH;
    const float* __restrict__ xr2 = xr1 + WIDTH;
    const float* __restrict__ xr3 = xr2 + WIDTH;

    ull val[64];

    // load: 4 rows, packed (row0,row1) -> h=0, (row2,row3) -> h=1
    // Only 2 float4 temps live at a time; fences bound hoisting.
#pragma unroll
    for (int vhi = 0; vhi < 8; vhi++) {
        int off = vhi * 128 + lane * 4;
        int s = vhi * 4;
        {
            float4 a = *(const float4*)(xr0 + off);
            float4 b = *(const float4*)(xr1 + off);
            val[(s + 0) * 2 + 0] = pk(a.x, b.x);
            val[(s + 1) * 2 + 0] = pk(a.y, b.y);
            val[(s + 2) * 2 + 0] = pk(a.z, b.z);
            val[(s + 3) * 2 + 0] = pk(a.w, b.w);
        }
        cfence();
        {
            float4 c = *(const float4*)(xr2 + off);
            float4 d = *(const float4*)(xr3 + off);
            val[(s + 0) * 2 + 1] = pk(c.x, d.x);
            val[(s + 1) * 2 + 1] = pk(c.y, d.y);
            val[(s + 2) * 2 + 1] = pk(c.z, d.z);
            val[(s + 3) * 2 + 1] = pk(c.w, d.w);
        }
        cfence();
    }

#pragma unroll 1
    for (int layer = 0; layer < DEPTH; layer++) {
        const float4* __restrict__ ct = g_ctab + layer * (BDEPTH * 512);
        reg_step<16>(val, lane, ct + 0 * 512);   // t=0: bit 9
        reg_step<8>(val, lane, ct + 1 * 512);    // t=1: bit 8
        reg_step<4>(val, lane, ct + 2 * 512);    // t=2: bit 7
        lane_step<16>(val, lane, ct + 3 * 512);  // t=3: bit 6
        lane_step<8>(val, lane, ct + 4 * 512);   // t=4: bit 5
        lane_step<4>(val, lane, ct + 5 * 512);   // t=5: bit 4
        lane_step<2>(val, lane, ct + 6 * 512);   // t=6: bit 3
        lane_step<1>(val, lane, ct + 7 * 512);   // t=7: bit 2
        reg_step<2>(val, lane, ct + 8 * 512);    // t=8: bit 1
        reg_step<1>(val, lane, ct + 9 * 512);    // t=9: bit 0
        if (layer < DEPTH - 1) quintic(val, lane, layer);
    }

    // store (final permutation is identity: 80 steps = 8 full index rotations)
    float* __restrict__ yr0 = Y + row0 * WIDTH;
    float* __restrict__ yr1 = yr0 + WIDTH;
    float* __restrict__ yr2 = yr1 + WIDTH;
    float* __restrict__ yr3 = yr2 + WIDTH;
#pragma unroll
    for (int vhi = 0; vhi < 8; vhi++) {
        int off = vhi * 128 + lane * 4;
        int s = vhi * 4;
        {
            float4 a, b;
            unpk(val[(s + 0) * 2 + 0], a.x, b.x);
            unpk(val[(s + 1) * 2 + 0], a.y, b.y);
            unpk(val[(s + 2) * 2 + 0], a.z, b.z);
            unpk(val[(s + 3) * 2 + 0], a.w, b.w);
            *(float4*)(yr0 + off) = a;
            *(float4*)(yr1 + off) = b;
        }
        cfence();
        {
            float4 c, d;
            unpk(val[(s + 0) * 2 + 1], c.x, d.x);
            unpk(val[(s + 1) * 2 + 1], c.y, d.y);
            unpk(val[(s + 2) * 2 + 1], c.z, d.z);
            unpk(val[(s + 3) * 2 + 1], c.w, d.w);
            *(float4*)(yr2 + off) = c;
            *(float4*)(yr3 + off) = d;
        }
        cfence();
    }
}

extern "C" void kernel_launch(void* const* d_in, const int* in_sizes, int n_in,
                              void* d_out, int out_size) {
    const float* X     = (const float*)d_in[0];
    const float* bp    = (const float*)d_in[1];
    const float* bias  = (const float*)d_in[2];
    const float* slope = (const float*)d_in[3];
    const float* scale = (const float*)d_in[4];
    float* Y = (float*)d_out;

    // ONE prep launch (2 launches total, so ncu -s 5 -c 1 profiles net_kernel)
    prep_all<<<(CT_ELEMS + Q_ELEMS + 255) / 256, 256>>>(bp, bias, slope, scale);
    // 4 rows per warp, 4 warps per CTA -> 16 rows per CTA
    net_kernel<<<BATCH / 16, 128>>>(X, Y);
}

// round 3
// speedup vs baseline: 1.3376x; 1.3310x over previous
#include <cuda_runtime.h>
#include <cstdint>

#define WIDTH  1024
#define HALF   512
#define DEPTH  8
#define BDEPTH 10
#define BATCH  65536

typedef unsigned long long ull;

// Butterfly coefficient table: (c, s) float2 per (step, entry).
//   reg-bit steps:  entry = pairidx*32 + lane        (512 entries/step)
//   lane-bit steps: entry = slot*16 + lanepair       (512 entries/step)
// Packed duplicates are rebuilt in-kernel with MOVs (trades alu for L1 bytes —
// L1 crossbar is the measured bottleneck at 74%).
__device__ float2 g_ctab[DEPTH * BDEPTH * 512];
// quintic params per (act_layer, slot*32+lane): (m,m,nb,nb) with m=slope/scale, nb=-bias/scale
__device__ float4 g_qa[(DEPTH - 1) * 1024];
// (scale, scale)
__device__ float2 g_qs[(DEPTH - 1) * 1024];

// ---------- f32x2 helpers ----------
__device__ __forceinline__ ull pk(float lo, float hi) {
    ull r;
    asm("mov.b64 %0, {%1, %2};" : "=l"(r) : "r"(__float_as_uint(lo)), "r"(__float_as_uint(hi)));
    return r;
}
__device__ __forceinline__ void unpk(ull v, float& lo, float& hi) {
    unsigned a, b;
    asm("mov.b64 {%0, %1}, %2;" : "=r"(a), "=r"(b) : "l"(v));
    lo = __uint_as_float(a);
    hi = __uint_as_float(b);
}
__device__ __forceinline__ ull f2mul(ull a, ull b) {
    ull r;
    asm("mul.rn.f32x2 %0, %1, %2;" : "=l"(r) : "l"(a), "l"(b));
    return r;
}
__device__ __forceinline__ ull f2fma(ull a, ull b, ull c) {
    ull r;
    asm("fma.rn.f32x2 %0, %1, %2, %3;" : "=l"(r) : "l"(a), "l"(b), "l"(c));
    return r;
}
// Compiler fence: bounds load hoisting / in-flight register pressure.
__device__ __forceinline__ void cfence() { asm volatile("" ::: "memory"); }

// ---------- prep: all coefficient tables in ONE launch ----------
// Element index p0 (10 bits) maps to (slot v in [0,32), lane l in [0,32)):
//   p0 = (v_hi << 7) | (l << 2) | v_lo   where v = (v_hi<<2)|v_lo
// Step t (in layer) pairs original bit b = 9 - t.
// theta index: j bit k = p0 bit ((k - t) mod 10), k=0..8; theta = bparams[layer][j][t].
#define CT_ELEMS (DEPTH * BDEPTH * 512)
#define Q_ELEMS  ((DEPTH - 1) * 1024)

__global__ void prep_all(const float* __restrict__ bp,
                         const float* __restrict__ bias,
                         const float* __restrict__ slope,
                         const float* __restrict__ scale) {
    int e = blockIdx.x * blockDim.x + threadIdx.x;
    if (e < CT_ELEMS) {
        int T = e >> 9;
        int idx = e & 511;
        int layer = T / BDEPTH;
        int t = T % BDEPTH;
        int b = 9 - t;

        int v0, l0;
        if (b >= 7 || b <= 1) {
            int sbit = (b >= 7) ? (b - 5) : b;
            int m = 1 << sbit;
            int pi = idx >> 5;
            l0 = idx & 31;
            v0 = (pi & (m - 1)) | ((pi & ~(m - 1)) << 1);
        } else {
            int lm = 1 << (b - 2);
            int v = idx >> 4;
            int lp = idx & 15;
            l0 = (lp & (lm - 1)) | ((lp & ~(lm - 1)) << 1);
            v0 = v;
        }
        int p0 = ((v0 >> 2) << 7) | (l0 << 2) | (v0 & 3);

        int j = 0;
#pragma unroll
        for (int k = 0; k < 9; k++) {
            int src = ((k - t) % 10 + 10) % 10;
            j |= ((p0 >> src) & 1) << k;
        }
        float theta = bp[layer * (HALF * BDEPTH) + j * BDEPTH + t];
        float s, c;
        sincosf(theta, &s, &c);
        g_ctab[e] = make_float2(c, s);
    } else if (e < CT_ELEMS + Q_ELEMS) {
        int q = e - CT_ELEMS;
        int act = q >> 10;
        int idx = q & 1023;
        int v = idx >> 5;
        int l = idx & 31;
        int p0 = ((v >> 2) << 7) | (l << 2) | (v & 3);
        float bi = bias[act * WIDTH + p0];
        float sl = slope[act * WIDTH + p0];
        float sc = scale[act * WIDTH + p0];
        g_qa[q] = make_float4(sl / sc, sl / sc, -bi / sc, -bi / sc);
        g_qs[q] = make_float2(sc, sc);
    }
}

// ---------- main kernel ----------
// Each warp processes 4 rows. Thread holds 32 slots x 2 f32x2 values (rows 0,1 | rows 2,3).
// val[v*2 + h].

template <int M>
__device__ __forceinline__ void reg_step(ull (&val)[64], int lane, const float2* __restrict__ ct) {
#pragma unroll
    for (int pi = 0; pi < 16; pi++) {
        const int v0 = (pi & (M - 1)) | ((pi & ~(M - 1)) << 1);
        const int v1 = v0 | M;
        float2 cs = __ldg(ct + pi * 32 + lane);
        ull c2 = pk(cs.x, cs.x);
        ull s2 = pk(cs.y, cs.y);
        ull ns2 = s2 ^ 0x8000000080000000ULL;
#pragma unroll
        for (int h = 0; h < 2; h++) {
            ull x0 = val[v0 * 2 + h];
            ull x1 = val[v1 * 2 + h];
            val[v0 * 2 + h] = f2fma(c2, x0, f2mul(s2, x1));   // n0 =  c*x0 + s*x1
            val[v1 * 2 + h] = f2fma(c2, x1, f2mul(ns2, x0));  // n1 =  c*x1 - s*x0
        }
        if ((pi & 3) == 3) cfence();
    }
}

template <int LM>
__device__ __forceinline__ void lane_step(ull (&val)[64], int lane, const float2* __restrict__ ct) {
    const ull smask = (lane & LM) ? 0x8000000080000000ULL : 0ULL;
    const int lp = (lane & (LM - 1)) | ((lane >> 1) & ~(LM - 1));
#pragma unroll
    for (int v = 0; v < 32; v++) {
        float2 cs = __ldg(ct + v * 16 + lp);
        ull c2 = pk(cs.x, cs.x);
        ull s2 = pk(cs.y, cs.y) ^ smask;
#pragma unroll
        for (int h = 0; h < 2; h++) {
            ull x = val[v * 2 + h];
            ull xp = __shfl_xor_sync(0xffffffffu, x, LM);
            val[v * 2 + h] = f2fma(c2, x, f2mul(s2, xp));
        }
        if ((v & 3) == 3) cfence();
    }
}

__device__ __forceinline__ void quintic(ull (&val)[64], int lane, int act) {
    const float4* __restrict__ qa = g_qa + act * 1024;
    const float2* __restrict__ qs = g_qs + act * 1024;
    const ull C1875 = 0x3FF000003FF00000ULL;  // (1.875, 1.875)
    const ull CM125 = 0xBFA00000BFA00000ULL;  // (-1.25, -1.25)
    const ull C0375 = 0x3EC000003EC00000ULL;  // (0.375, 0.375)
#pragma unroll
    for (int v = 0; v < 32; v++) {
        float4 aq = __ldg(qa + v * 32 + lane);
        float2 sq = __ldg(qs + v * 32 + lane);
        ull m2 = pk(aq.x, aq.y);
        ull nb2 = pk(aq.z, aq.w);
        ull sc2 = pk(sq.x, sq.y);
#pragma unroll
        for (int h = 0; h < 2; h++) {
            ull u = f2fma(val[v * 2 + h], m2, nb2);
            float lo, hi;
            unpk(u, lo, hi);
            lo = fminf(fmaxf(lo, -1.0f), 1.0f);
            hi = fminf(fmaxf(hi, -1.0f), 1.0f);
            u = pk(lo, hi);
            ull u2 = f2mul(u, u);
            ull p = f2fma(u2, C0375, CM125);
            p = f2fma(u2, p, C1875);
            ull r = f2mul(u, p);
            val[v * 2 + h] = f2mul(r, sc2);
        }
        if ((v & 7) == 7) cfence();
    }
}

__global__ void __launch_bounds__(128, 1)
net_kernel(const float* __restrict__ X, float* __restrict__ Y) {
    const int lane = threadIdx.x & 31;
    const int w = blockIdx.x * 4 + (threadIdx.x >> 5);
    const long long row0 = (long long)w * 4;
    const float* __restrict__ xr0 = X + row0 * WIDTH;
    const float* __restrict__ xr1 = xr0 + WIDTH;
    const float* __restrict__ xr2 = xr1 + WIDTH;
    const float* __restrict__ xr3 = xr2 + WIDTH;

    ull val[64];

    // load: 4 rows, packed (row0,row1) -> h=0, (row2,row3) -> h=1
#pragma unroll
    for (int vhi = 0; vhi < 8; vhi++) {
        int off = vhi * 128 + lane * 4;
        int s = vhi * 4;
        {
            float4 a = *(const float4*)(xr0 + off);
            float4 b = *(const float4*)(xr1 + off);
            val[(s + 0) * 2 + 0] = pk(a.x, b.x);
            val[(s + 1) * 2 + 0] = pk(a.y, b.y);
            val[(s + 2) * 2 + 0] = pk(a.z, b.z);
            val[(s + 3) * 2 + 0] = pk(a.w, b.w);
        }
        cfence();
        {
            float4 c = *(const float4*)(xr2 + off);
            float4 d = *(const float4*)(xr3 + off);
            val[(s + 0) * 2 + 1] = pk(c.x, d.x);
            val[(s + 1) * 2 + 1] = pk(c.y, d.y);
            val[(s + 2) * 2 + 1] = pk(c.z, d.z);
            val[(s + 3) * 2 + 1] = pk(c.w, d.w);
        }
        cfence();
    }

#pragma unroll 1
    for (int layer = 0; layer < DEPTH; layer++) {
        const float2* __restrict__ ct = g_ctab + layer * (BDEPTH * 512);
        reg_step<16>(val, lane, ct + 0 * 512);   // t=0: bit 9
        reg_step<8>(val, lane, ct + 1 * 512);    // t=1: bit 8
        reg_step<4>(val, lane, ct + 2 * 512);    // t=2: bit 7
        lane_step<16>(val, lane, ct + 3 * 512);  // t=3: bit 6
        lane_step<8>(val, lane, ct + 4 * 512);   // t=4: bit 5
        lane_step<4>(val, lane, ct + 5 * 512);   // t=5: bit 4
        lane_step<2>(val, lane, ct + 6 * 512);   // t=6: bit 3
        lane_step<1>(val, lane, ct + 7 * 512);   // t=7: bit 2
        reg_step<2>(val, lane, ct + 8 * 512);    // t=8: bit 1
        reg_step<1>(val, lane, ct + 9 * 512);    // t=9: bit 0
        if (layer < DEPTH - 1) quintic(val, lane, layer);
    }

    // store (final permutation is identity: 80 steps = 8 full index rotations)
    float* __restrict__ yr0 = Y + row0 * WIDTH;
    float* __restrict__ yr1 = yr0 + WIDTH;
    float* __restrict__ yr2 = yr1 + WIDTH;
    float* __restrict__ yr3 = yr2 + WIDTH;
#pragma unroll
    for (int vhi = 0; vhi < 8; vhi++) {
        int off = vhi * 128 + lane * 4;
        int s = vhi * 4;
        {
            float4 a, b;
            unpk(val[(s + 0) * 2 + 0], a.x, b.x);
            unpk(val[(s + 1) * 2 + 0], a.y, b.y);
            unpk(val[(s + 2) * 2 + 0], a.z, b.z);
            unpk(val[(s + 3) * 2 + 0], a.w, b.w);
            *(float4*)(yr0 + off) = a;
            *(float4*)(yr1 + off) = b;
        }
        cfence();
        {
            float4 c, d;
            unpk(val[(s + 0) * 2 + 1], c.x, d.x);
            unpk(val[(s + 1) * 2 + 1], c.y, d.y);
            unpk(val[(s + 2) * 2 + 1], c.z, d.z);
            unpk(val[(s + 3) * 2 + 1], c.w, d.w);
            *(float4*)(yr2 + off) = c;
            *(float4*)(yr3 + off) = d;
        }
        cfence();
    }
}

extern "C" void kernel_launch(void* const* d_in, const int* in_sizes, int n_in,
                              void* d_out, int out_size) {
    const float* X     = (const float*)d_in[0];
    const float* bp    = (const float*)d_in[1];
    const float* bias  = (const float*)d_in[2];
    const float* slope = (const float*)d_in[3];
    const float* scale = (const float*)d_in[4];
    float* Y = (float*)d_out;

    // ONE prep launch (2 launches total, so ncu -s 5 -c 1 profiles net_kernel)
    prep_all<<<(CT_ELEMS + Q_ELEMS + 255) / 256, 256>>>(bp, bias, slope, scale);
    // 4 rows per warp, 4 warps per CTA -> 16 rows per CTA
    net_kernel<<<BATCH / 16, 128>>>(X, Y);
}